// round 1
// baseline (speedup 1.0000x reference)
#include <cuda_runtime.h>
#include <cstdint>

#define NB 4
#define H  512
#define W  360
#define D  512
#define HW (H*W)           // 184320
#define DD (D*D)           // 262144
#define WLEN   48
#define STAGES 4

// ---- device scratch (no allocations allowed) ----
__device__ float4 g_pk[W * H];     // packed filtered columns: [w][i] = {b0,b1,b2,b3}
__device__ float  g_Ft[H * H];     // F^T: Ft[j*512 + i] = hG[(j - i - 257) & 511]
__device__ float4 g_coef[W];       // per-angle {A, B, C0, minAB}

// ============================================================
// Prep: build F^T and per-angle affine coefficients
// py(X,Y) = C0 + A*X + B*Y, derived from probe reads of t_y
// ============================================================
__global__ void prep_kernel(const float* __restrict__ hG,
                            const float* __restrict__ t_y) {
    int idx = blockIdx.x * 256 + threadIdx.x;
    if (idx < H * H) {
        int j = idx >> 9;
        int i = idx & (H - 1);
        g_Ft[idx] = hG[(j - i - 257) & (H - 1)];
    }
    if (idx < W) {
        // t_y[w, 256, 257] = cos/256 ; t_y[w, 257, 256] = -sin/256
        float cosv =  256.0f * t_y[idx * DD + 256 * D + 257];
        float sinv = -256.0f * t_y[idx * DD + 257 * D + 256];
        const float s = 255.5f / 256.0f;
        float A = -s * sinv;
        float B =  s * cosv;
        float C0 = 255.5f - 256.0f * B - 256.0f * A;
        float minAB = fminf(A * 31.0f, 0.0f) + fminf(B * 31.0f, 0.0f);
        g_coef[idx] = make_float4(A, B, C0, minAB);
    }
}

// ============================================================
// Filter: C[i, c] = sum_j Ft[j][i] * X[j, c],  c = w*4 + n
// BM=64 (i), BN=64 (c), BK=16, 256 threads, 4x4 per thread.
// Output written batch-packed into g_pk[w][i].
// ============================================================
__global__ __launch_bounds__(256) void filter_kernel(const float* __restrict__ x) {
    __shared__ float Fs[16][64];
    __shared__ float Xs[16][64];

    int tid = threadIdx.x;
    int tx = tid & 15;          // i sub-tile
    int ty = tid >> 4;          // c sub-tile (also staging k-row)
    int iblk = blockIdx.x * 64;
    int cblk = blockIdx.y * 64;

    int lk  = ty;               // staging row 0..15
    int lo4 = tx * 4;           // staging col offset

    int wst = (cblk + lo4) >> 2;       // staging w
    bool okw = (wst < W);

    const float* Fg = g_Ft + iblk + lo4;
    const float* Xg = x + wst;

    // prefetch k0 = 0
    float4 fv = *(const float4*)(Fg + lk * H);
    float xv0 = 0.f, xv1 = 0.f, xv2 = 0.f, xv3 = 0.f;
    if (okw) {
        xv0 = Xg[0 * HW + lk * W];
        xv1 = Xg[1 * HW + lk * W];
        xv2 = Xg[2 * HW + lk * W];
        xv3 = Xg[3 * HW + lk * W];
    }

    float acc[4][4] = {};

    for (int k0 = 0; k0 < H; k0 += 16) {
        __syncthreads();
        *(float4*)&Fs[lk][lo4] = fv;
        Xs[lk][lo4 + 0] = xv0;
        Xs[lk][lo4 + 1] = xv1;
        Xs[lk][lo4 + 2] = xv2;
        Xs[lk][lo4 + 3] = xv3;
        __syncthreads();

        int kn = k0 + 16;
        if (kn < H) {
            fv = *(const float4*)(Fg + (kn + lk) * H);
            if (okw) {
                xv0 = Xg[0 * HW + (kn + lk) * W];
                xv1 = Xg[1 * HW + (kn + lk) * W];
                xv2 = Xg[2 * HW + (kn + lk) * W];
                xv3 = Xg[3 * HW + (kn + lk) * W];
            }
        }

        #pragma unroll
        for (int k = 0; k < 16; ++k) {
            float4 a  = *(const float4*)&Fs[k][tx * 4];
            float4 b4 = *(const float4*)&Xs[k][ty * 4];
            acc[0][0] = fmaf(a.x, b4.x, acc[0][0]);
            acc[0][1] = fmaf(a.x, b4.y, acc[0][1]);
            acc[0][2] = fmaf(a.x, b4.z, acc[0][2]);
            acc[0][3] = fmaf(a.x, b4.w, acc[0][3]);
            acc[1][0] = fmaf(a.y, b4.x, acc[1][0]);
            acc[1][1] = fmaf(a.y, b4.y, acc[1][1]);
            acc[1][2] = fmaf(a.y, b4.z, acc[1][2]);
            acc[1][3] = fmaf(a.y, b4.w, acc[1][3]);
            acc[2][0] = fmaf(a.z, b4.x, acc[2][0]);
            acc[2][1] = fmaf(a.z, b4.y, acc[2][1]);
            acc[2][2] = fmaf(a.z, b4.z, acc[2][2]);
            acc[2][3] = fmaf(a.z, b4.w, acc[2][3]);
            acc[3][0] = fmaf(a.w, b4.x, acc[3][0]);
            acc[3][1] = fmaf(a.w, b4.y, acc[3][1]);
            acc[3][2] = fmaf(a.w, b4.z, acc[3][2]);
            acc[3][3] = fmaf(a.w, b4.w, acc[3][3]);
        }
    }

    // store: thread's 4 c-values are exactly batches 0..3 of one w
    int wout = (cblk >> 2) + ty;
    if (wout < W) {
        #pragma unroll
        for (int ii = 0; ii < 4; ++ii) {
            g_pk[wout * H + iblk + tx * 4 + ii] =
                make_float4(acc[ii][0], acc[ii][1], acc[ii][2], acc[ii][3]);
        }
    }
}

// ============================================================
// Backprojection
// ============================================================
__device__ __forceinline__ void stage_angle(int w, int tid, float X0f, float Y0f,
                                            float4* sbuf) {
    float4 cf = g_coef[w];
    float pymin = fmaf(cf.x, X0f, fmaf(cf.y, Y0f, cf.z)) + cf.w;
    int lo = __float2int_rd(pymin) - 1;
    if (tid < WLEN) {
        int g = lo + tid;
        unsigned ok = ((unsigned)g < (unsigned)H) ? 16u : 0u;
        int gc = g < 0 ? 0 : (g > H - 1 ? H - 1 : g);
        const float4* src = g_pk + (w * H + gc);
        unsigned sa = (unsigned)__cvta_generic_to_shared(sbuf + tid);
        asm volatile("cp.async.cg.shared.global [%0], [%1], 16, %2;\n"
                     :: "r"(sa), "l"(src), "r"(ok));
    }
    asm volatile("cp.async.commit_group;\n" ::: "memory");
}

__global__ __launch_bounds__(256, 2) void backproj_kernel(float* __restrict__ out) {
    __shared__ float4 sb[STAGES][WLEN];

    int tid  = threadIdx.x;
    int lane = tid & 31;
    int warp = tid >> 5;
    int lx = lane >> 2;       // 0..7  (X within warp footprint)
    int ly = lane & 3;        // 0..3  (Y within warp footprint)

    int X0 = blockIdx.x * 32;
    int Y0 = blockIdx.y * 32;
    float X0f = (float)X0, Y0f = (float)Y0;

    int Xt = X0 + lx;                 // + s*8 per slot
    int Yt = Y0 + warp * 4 + ly;
    float Xtf = (float)Xt, Ytf = (float)Yt;

    float acc[4][4] = {};             // [slot][batch]

    // prologue: stage angles 0..2
    stage_angle(0, tid, X0f, Y0f, sb[0]);
    stage_angle(1, tid, X0f, Y0f, sb[1]);
    stage_angle(2, tid, X0f, Y0f, sb[2]);

    for (int w = 0; w < W; ++w) {
        asm volatile("cp.async.wait_group 2;\n" ::: "memory");
        __syncthreads();

        int wn = w + 3;
        if (wn < W) {
            stage_angle(wn, tid, X0f, Y0f, sb[wn & (STAGES - 1)]);
        } else {
            asm volatile("cp.async.commit_group;\n" ::: "memory");
        }

        // compute this angle
        float4 cf = g_coef[w];
        float pymin = fmaf(cf.x, X0f, fmaf(cf.y, Y0f, cf.z)) + cf.w;
        int lo = __float2int_rd(pymin) - 1;
        float py = fmaf(cf.x, Xtf, fmaf(cf.y, Ytf, cf.z)) - (float)lo;
        float A8 = cf.x * 8.0f;
        const float4* bp = sb[w & (STAGES - 1)];

        #pragma unroll
        for (int s = 0; s < 4; ++s) {
            int   y0 = __float2int_rd(py);
            float fy = py - (float)y0;
            float w0 = 1.0f - fy;
            float4 v0 = bp[y0];
            float4 v1 = bp[y0 + 1];
            acc[s][0] = fmaf(v1.x, fy, fmaf(v0.x, w0, acc[s][0]));
            acc[s][1] = fmaf(v1.y, fy, fmaf(v0.y, w0, acc[s][1]));
            acc[s][2] = fmaf(v1.z, fy, fmaf(v0.z, w0, acc[s][2]));
            acc[s][3] = fmaf(v1.w, fy, fmaf(v0.w, w0, acc[s][3]));
            py += A8;
        }
    }

    const float scale = 0.004363323129985824f;  // pi / 720
    #pragma unroll
    for (int s = 0; s < 4; ++s) {
        int X = Xt + s * 8;
        int o = X * D + Yt;
        #pragma unroll
        for (int n = 0; n < NB; ++n) {
            out[n * DD + o] = acc[s][n] * scale;
        }
    }
}

extern "C" void kernel_launch(void* const* d_in, const int* in_sizes, int n_in,
                              void* d_out, int out_size) {
    const float* radon = (const float*)d_in[0];
    const float* hG    = (const float*)d_in[1];
    const float* t_y   = (const float*)d_in[2];
    float* out = (float*)d_out;

    prep_kernel<<<1024, 256>>>(hG, t_y);
    filter_kernel<<<dim3(8, 23), 256>>>(radon);
    backproj_kernel<<<dim3(16, 16), 256>>>(out);
}

// round 3
// speedup vs baseline: 1.2110x; 1.2110x over previous
#include <cuda_runtime.h>
#include <cstdint>

#define NB 4
#define H  512
#define W  360
#define D  512
#define HW (H*W)           // 184320
#define DD (D*D)           // 262144
#define WLEN 48
#define NSTG 8             // stage buffers = 4 pairs in ring

// ---- device scratch (no allocations allowed) ----
__device__ float4 g_pk[W * H];     // packed filtered columns: [w][i] = {b0,b1,b2,b3}

// ============================================================
// Filter: C[i, c] = sum_j F[i][j] * X[j, c],  c = w*4 + n
// F[i][j] = hG[(j - i - 257) & 511]  (computed on the fly from smem hG)
// BM=64 (i), BN=64 (c), BK=16, 256 threads, 4x4 per thread.
// Output written batch-packed into g_pk[w][i].
// ============================================================
__global__ __launch_bounds__(256) void filter_kernel(const float* __restrict__ x,
                                                     const float* __restrict__ hG) {
    __shared__ float hs[512];
    __shared__ float Fs[16][64];
    __shared__ float Xs[16][64];

    int tid = threadIdx.x;
    hs[tid]       = hG[tid];
    hs[tid + 256] = hG[tid + 256];

    int tx = tid & 15;          // i sub-tile
    int ty = tid >> 4;          // c sub-tile (also staging k-row)
    int iblk = blockIdx.x * 64;
    int cblk = blockIdx.y * 64;

    int lk  = ty;               // staging row 0..15
    int lo4 = tx * 4;           // staging col offset

    int wst = (cblk + lo4) >> 2;       // staging w
    bool okw = (wst < W);
    const float* Xg = x + wst;

    int jb0 = -(iblk + lo4) - 257;     // base index offset for F row

    __syncthreads();                   // hs ready

    // prefetch k0 = 0   (row j = lk)
    float4 fv;
    {
        int b = jb0 + lk;
        fv.x = hs[(b    ) & 511];
        fv.y = hs[(b - 1) & 511];
        fv.z = hs[(b - 2) & 511];
        fv.w = hs[(b - 3) & 511];
    }
    float xv0 = 0.f, xv1 = 0.f, xv2 = 0.f, xv3 = 0.f;
    if (okw) {
        xv0 = Xg[0 * HW + lk * W];
        xv1 = Xg[1 * HW + lk * W];
        xv2 = Xg[2 * HW + lk * W];
        xv3 = Xg[3 * HW + lk * W];
    }

    float acc[4][4] = {};

    for (int k0 = 0; k0 < H; k0 += 16) {
        __syncthreads();
        *(float4*)&Fs[lk][lo4] = fv;
        Xs[lk][lo4 + 0] = xv0;
        Xs[lk][lo4 + 1] = xv1;
        Xs[lk][lo4 + 2] = xv2;
        Xs[lk][lo4 + 3] = xv3;
        __syncthreads();

        int kn = k0 + 16;
        if (kn < H) {
            int b = jb0 + kn + lk;
            fv.x = hs[(b    ) & 511];
            fv.y = hs[(b - 1) & 511];
            fv.z = hs[(b - 2) & 511];
            fv.w = hs[(b - 3) & 511];
            if (okw) {
                xv0 = Xg[0 * HW + (kn + lk) * W];
                xv1 = Xg[1 * HW + (kn + lk) * W];
                xv2 = Xg[2 * HW + (kn + lk) * W];
                xv3 = Xg[3 * HW + (kn + lk) * W];
            }
        }

        #pragma unroll
        for (int k = 0; k < 16; ++k) {
            float4 a  = *(const float4*)&Fs[k][tx * 4];
            float4 b4 = *(const float4*)&Xs[k][ty * 4];
            acc[0][0] = fmaf(a.x, b4.x, acc[0][0]);
            acc[0][1] = fmaf(a.x, b4.y, acc[0][1]);
            acc[0][2] = fmaf(a.x, b4.z, acc[0][2]);
            acc[0][3] = fmaf(a.x, b4.w, acc[0][3]);
            acc[1][0] = fmaf(a.y, b4.x, acc[1][0]);
            acc[1][1] = fmaf(a.y, b4.y, acc[1][1]);
            acc[1][2] = fmaf(a.y, b4.z, acc[1][2]);
            acc[1][3] = fmaf(a.y, b4.w, acc[1][3]);
            acc[2][0] = fmaf(a.z, b4.x, acc[2][0]);
            acc[2][1] = fmaf(a.z, b4.y, acc[2][1]);
            acc[2][2] = fmaf(a.z, b4.z, acc[2][2]);
            acc[2][3] = fmaf(a.z, b4.w, acc[2][3]);
            acc[3][0] = fmaf(a.w, b4.x, acc[3][0]);
            acc[3][1] = fmaf(a.w, b4.y, acc[3][1]);
            acc[3][2] = fmaf(a.w, b4.z, acc[3][2]);
            acc[3][3] = fmaf(a.w, b4.w, acc[3][3]);
        }
    }

    // store: thread's 4 c-values are exactly batches 0..3 of one w
    int wout = (cblk >> 2) + ty;
    if (wout < W) {
        #pragma unroll
        for (int ii = 0; ii < 4; ++ii) {
            g_pk[wout * H + iblk + tx * 4 + ii] =
                make_float4(acc[ii][0], acc[ii][1], acc[ii][2], acc[ii][3]);
        }
    }
}

// ============================================================
// Backprojection: 32x32 tile per CTA, 4 batches packed in float4,
// 2 angles per iteration, 8-buffer cp.async ring.
// py(X,Y) = C0 + A*X + B*Y  (affine per angle)
// ============================================================
__device__ __forceinline__ void stage_pair(int w, int tid, float X0f, float Y0f,
                                           const float4* scoef,
                                           float4 (*sb)[WLEN]) {
    if (tid < 2 * WLEN) {
        int a   = (tid >= WLEN) ? 1 : 0;
        int idx = tid - (a ? WLEN : 0);
        int wa  = w + a;
        float4 cf = scoef[wa];
        float pymin = fmaf(cf.x, X0f, fmaf(cf.y, Y0f, cf.z)) + cf.w;
        int lo = __float2int_rd(pymin) - 1;
        int g = lo + idx;
        unsigned ok = ((unsigned)g < (unsigned)H) ? 16u : 0u;
        int gc = g < 0 ? 0 : (g > H - 1 ? H - 1 : g);
        const float4* src = g_pk + (wa * H + gc);
        unsigned sa = (unsigned)__cvta_generic_to_shared(&sb[wa & (NSTG - 1)][idx]);
        asm volatile("cp.async.cg.shared.global [%0], [%1], 16, %2;\n"
                     :: "r"(sa), "l"(src), "r"(ok));
    }
    asm volatile("cp.async.commit_group;\n" ::: "memory");
}

__device__ __forceinline__ void bp_angle(const float4* __restrict__ scoef, int w,
                                         const float4* __restrict__ bp,
                                         float X0f, float Y0f,
                                         float Xtf, float Ytf,
                                         float acc[4][4]) {
    float4 cf = scoef[w];
    float pymin = fmaf(cf.x, X0f, fmaf(cf.y, Y0f, cf.z)) + cf.w;
    int lo = __float2int_rd(pymin) - 1;
    float py = fmaf(cf.x, Xtf, fmaf(cf.y, Ytf, cf.z)) - (float)lo;
    float A8 = cf.x * 8.0f;

    #pragma unroll
    for (int s = 0; s < 4; ++s) {
        int   y0 = __float2int_rd(py);
        float fy = py - (float)y0;
        float w0 = 1.0f - fy;
        float4 v0 = bp[y0];
        float4 v1 = bp[y0 + 1];
        acc[s][0] = fmaf(v1.x, fy, fmaf(v0.x, w0, acc[s][0]));
        acc[s][1] = fmaf(v1.y, fy, fmaf(v0.y, w0, acc[s][1]));
        acc[s][2] = fmaf(v1.z, fy, fmaf(v0.z, w0, acc[s][2]));
        acc[s][3] = fmaf(v1.w, fy, fmaf(v0.w, w0, acc[s][3]));
        py += A8;
    }
}

__global__ __launch_bounds__(256) void backproj_kernel(const float* __restrict__ t_y,
                                                       float* __restrict__ out) {
    __shared__ float4 scoef[W];
    __shared__ float4 sb[NSTG][WLEN];

    int tid  = threadIdx.x;
    int lane = tid & 31;
    int warp = tid >> 5;
    int lx = lane >> 2;       // 0..7  (X within warp footprint)
    int ly = lane & 3;        // 0..3  (Y within warp footprint)

    // per-angle affine coefficients from two probe reads of t_y
    for (int w = tid; w < W; w += 256) {
        float cosv =  256.0f * __ldg(&t_y[w * DD + 256 * D + 257]);
        float sinv = -256.0f * __ldg(&t_y[w * DD + 257 * D + 256]);
        const float s = 255.5f / 256.0f;
        float A = -s * sinv;
        float B =  s * cosv;
        float C0 = 255.5f - 256.0f * B - 256.0f * A;
        float minAB = fminf(A * 31.0f, 0.0f) + fminf(B * 31.0f, 0.0f);
        scoef[w] = make_float4(A, B, C0, minAB);
    }
    __syncthreads();

    int X0 = blockIdx.x * 32;
    int Y0 = blockIdx.y * 32;
    float X0f = (float)X0, Y0f = (float)Y0;

    int Xt = X0 + lx;                 // + s*8 per slot
    int Yt = Y0 + warp * 4 + ly;
    float Xtf = (float)Xt, Ytf = (float)Yt;

    float acc[4][4] = {};             // [slot][batch]

    // prologue: stage pairs (0,1), (2,3), (4,5)
    stage_pair(0, tid, X0f, Y0f, scoef, sb);
    stage_pair(2, tid, X0f, Y0f, scoef, sb);
    stage_pair(4, tid, X0f, Y0f, scoef, sb);

    for (int w = 0; w < W; w += 2) {
        asm volatile("cp.async.wait_group 2;\n" ::: "memory");
        __syncthreads();

        int wn = w + 6;
        if (wn < W) {
            stage_pair(wn, tid, X0f, Y0f, scoef, sb);
        } else {
            asm volatile("cp.async.commit_group;\n" ::: "memory");
        }

        bp_angle(scoef, w,     sb[w & (NSTG - 1)],       X0f, Y0f, Xtf, Ytf, acc);
        bp_angle(scoef, w + 1, sb[(w + 1) & (NSTG - 1)], X0f, Y0f, Xtf, Ytf, acc);
    }

    const float scale = 0.004363323129985824f;  // pi / 720
    #pragma unroll
    for (int s = 0; s < 4; ++s) {
        int X = Xt + s * 8;
        int o = X * D + Yt;
        #pragma unroll
        for (int n = 0; n < NB; ++n) {
            out[n * DD + o] = acc[s][n] * scale;
        }
    }
}

extern "C" void kernel_launch(void* const* d_in, const int* in_sizes, int n_in,
                              void* d_out, int out_size) {
    const float* radon = (const float*)d_in[0];
    const float* hG    = (const float*)d_in[1];
    const float* t_y   = (const float*)d_in[2];
    float* out = (float*)d_out;

    filter_kernel<<<dim3(8, 23), 256>>>(radon, hG);
    backproj_kernel<<<dim3(16, 16), 256>>>(t_y, out);
}